// round 2
// baseline (speedup 1.0000x reference)
#include <cuda_runtime.h>
#include <math.h>

#define NN    4096
#define EE    131072
#define ETOT  (EE + NN)
#define NEG_SLOPE 0.2f
#define NBLK  256
#define NTHR  256
#define NTOT  (NBLK * NTHR)

// ---------------- scratch (device globals; no allocation) ----------------
__device__ float              g_z[NN * 3];
__device__ float              g_zs[NN];
__device__ float              g_zd[NN];
__device__ float              g_ssum[NN];
__device__ float              g_acc[NN * 3];
__device__ float              g_acc3[NN];
__device__ float              g_w[NN];        // exp(o_i) per node
__device__ float              g_xf[NN];
__device__ unsigned long long g_ckey[NN];
__device__ unsigned long long g_skey;
__device__ float              g_sumexp;
__device__ float              g_p12;

// grid barrier state (self-resetting: count returns to 0 each barrier; gen monotonic)
__device__ unsigned           g_count = 0;
__device__ volatile unsigned  g_gen   = 0;

__device__ __forceinline__ void gsync() {
    __syncthreads();
    if (threadIdx.x == 0) {
        __threadfence();                       // release my writes
        unsigned g   = g_gen;                  // read BEFORE arriving
        unsigned old = atomicAdd(&g_count, 1u);
        if (old == (unsigned)(gridDim.x - 1)) {
            g_count = 0;
            __threadfence();
            g_gen = g + 1;
        } else {
            while (g_gen == g) { }
            __threadfence();                   // acquire
        }
    }
    __syncthreads();
}

// float -> totally-ordered uint (preserves ordering incl. negatives)
__device__ __forceinline__ unsigned int fenc(float f) {
    unsigned int u = __float_as_uint(f);
    return (u & 0x80000000u) ? ~u : (u | 0x80000000u);
}
__device__ __forceinline__ float leaky(float x) { return x >= 0.0f ? x : NEG_SLOPE * x; }

__global__ __launch_bounds__(NTHR)
void gat_fused(const float* __restrict__ x,    const int* __restrict__ ei,
               const float* __restrict__ W1,   const float* __restrict__ as1,
               const float* __restrict__ ad1,  const float* __restrict__ b1,
               const float* __restrict__ W2,   const float* __restrict__ as2,
               const float* __restrict__ ad2,  const float* __restrict__ b2,
               const float* __restrict__ W3,   const float* __restrict__ as3,
               const float* __restrict__ ad3,  const float* __restrict__ b3,
               const float* __restrict__ phi1, const float* __restrict__ phi2,
               float* __restrict__ out, int out_size) {
    const int tid = blockIdx.x * NTHR + threadIdx.x;   // 0..NTOT-1

    // ---- P0: layer-1 prep + zero all reduction state ----
    if (tid < NN) {
        float xi = x[tid];
        float zs = 0.f, zd = 0.f;
#pragma unroll
        for (int k = 0; k < 3; k++) {
            float z = xi * W1[k];
            g_z[tid * 3 + k]   = z;
            g_acc[tid * 3 + k] = 0.f;
            zs += z * as1[k];
            zd += z * ad1[k];
        }
        g_zs[tid] = zs; g_zd[tid] = zd;
        g_ssum[tid] = 0.f;
        g_ckey[tid] = 0ull;
    }
    if (tid == 0) { g_skey = 0ull; g_sumexp = 0.f; }
    gsync();

    // ---- P1: edge pass layer 1 (no segment max needed: softmax is shift-invariant) ----
    for (int t = tid; t < ETOT; t += NTOT) {
        int s, d;
        if (t < EE) { s = __ldg(ei + t); d = __ldg(ei + EE + t); } else { s = t - EE; d = s; }
        float e = leaky(__ldcg(g_zs + s) + __ldcg(g_zd + d));
        float w = __expf(e);
        atomicAdd(&g_ssum[d], w);
#pragma unroll
        for (int k = 0; k < 3; k++)
            atomicAdd(&g_acc[d * 3 + k], w * __ldcg(g_z + s * 3 + k));
    }
    gsync();

    // ---- P2: finalize layer 1, prep layer 2 ----
    if (tid < NN) {
        float inv = 1.0f / (__ldcg(g_ssum + tid) + 1e-16f);
        float h[3];
#pragma unroll
        for (int k = 0; k < 3; k++) {
            float v = __ldcg(g_acc + tid * 3 + k) * inv + b1[k];
            h[k] = v > 0.f ? v : 0.f;
        }
        float zs = 0.f, zd = 0.f;
#pragma unroll
        for (int k = 0; k < 3; k++) {
            float z = 0.f;
#pragma unroll
            for (int c = 0; c < 3; c++) z += h[c] * W2[k * 3 + c];
            g_z[tid * 3 + k]   = z;
            g_acc[tid * 3 + k] = 0.f;
            zs += z * as2[k];
            zd += z * ad2[k];
        }
        g_zs[tid] = zs; g_zd[tid] = zd;
        g_ssum[tid] = 0.f;
    }
    gsync();

    // ---- P3: edge pass layer 2 ----
    for (int t = tid; t < ETOT; t += NTOT) {
        int s, d;
        if (t < EE) { s = __ldg(ei + t); d = __ldg(ei + EE + t); } else { s = t - EE; d = s; }
        float e = leaky(__ldcg(g_zs + s) + __ldcg(g_zd + d));
        float w = __expf(e);
        atomicAdd(&g_ssum[d], w);
#pragma unroll
        for (int k = 0; k < 3; k++)
            atomicAdd(&g_acc[d * 3 + k], w * __ldcg(g_z + s * 3 + k));
    }
    gsync();

    // ---- P4: finalize layer 2, prep layer 3 (HID=1) ----
    if (tid < NN) {
        float inv = 1.0f / (__ldcg(g_ssum + tid) + 1e-16f);
        float z = 0.f;
#pragma unroll
        for (int c = 0; c < 3; c++) {
            float v = __ldcg(g_acc + tid * 3 + c) * inv + b2[c];
            float h = v > 0.f ? v : 0.f;
            z += h * W3[c];
        }
        g_z[tid]    = z;          // stride-1 reuse
        g_zs[tid]   = z * as3[0];
        g_zd[tid]   = z * ad3[0];
        g_acc3[tid] = 0.f;
        g_ssum[tid] = 0.f;
    }
    gsync();

    // ---- P5: edge pass layer 3 ----
    for (int t = tid; t < ETOT; t += NTOT) {
        int s, d;
        if (t < EE) { s = __ldg(ei + t); d = __ldg(ei + EE + t); } else { s = t - EE; d = s; }
        float e = leaky(__ldcg(g_zs + s) + __ldcg(g_zd + d));
        float w = __expf(e);
        atomicAdd(&g_ssum[d], w);
        atomicAdd(&g_acc3[d], w * __ldcg(g_z + s));
    }
    gsync();

    // ---- P6: node logits -> exp, grid sum; p12 dot (deterministic warp reduce) ----
    if (tid < NN) {
        float o = __ldcg(g_acc3 + tid) / (__ldcg(g_ssum + tid) + 1e-16f) + b3[0];
        float w = expf(o);
        g_w[tid] = w;
        atomicAdd(&g_sumexp, w);
    }
    if (blockIdx.x == 0 && threadIdx.x < 32) {
        int l = threadIdx.x;
        float p = 0.f;
#pragma unroll
        for (int k = 0; k < 4; k++) p += phi1[l + 32 * k] * phi2[l + 32 * k];
#pragma unroll
        for (int off = 16; off > 0; off >>= 1)
            p += __shfl_down_sync(0xFFFFFFFFu, p, off);
        if (l == 0) g_p12 = p;
    }
    gsync();

    // ---- P7: normalize (softmax out), argmax(start) via 64-bit key ----
    if (tid < NN) {
        float xo = g_w[tid] / __ldcg(&g_sumexp);
        out[tid]  = xo;
        g_xf[tid] = xo;
        unsigned long long key =
            ((unsigned long long)fenc(xo) << 32) |
            (unsigned long long)(0xFFFFFFFFu - (unsigned)tid);
        atomicMax(&g_skey, key);
    }
    gsync();

    // ---- P8: chain scores -> per-source argmax key ----
    {
        const float scale = 1.0f / sqrtf(128.0f);
        float p12 = __ldcg(&g_p12);
        for (int j = tid; j < EE; j += NTOT) {
            int s = __ldg(ei + j), d = __ldg(ei + EE + j);
            float t = ((p12 * __ldcg(g_xf + s)) * __ldcg(g_xf + d)) * scale;
            float sc = tanhf(t);
            unsigned long long key =
                ((unsigned long long)fenc(sc) << 32) |
                (unsigned long long)(0xFFFFFFFFu - (unsigned)j);
            atomicMax(&g_ckey[s], key);
        }
    }
    gsync();

    // ---- P9: block 0 resolves next[] and pointer-doubles the 4096-step walk ----
    if (blockIdx.x == 0) {
        __shared__ int A[NN];
        __shared__ int B[NN];
        for (int i = threadIdx.x; i < NN; i += NTHR) {
            unsigned long long key = __ldcg(&g_ckey[i]);
            int j = key ? (int)(0xFFFFFFFFu - (unsigned)(key & 0xFFFFFFFFull)) : 0;
            A[i] = __ldg(ei + EE + j);
        }
        __syncthreads();
        for (int it = 0; it < 12; it++) {          // next^(2^12) = next^4096
            for (int i = threadIdx.x; i < NN; i += NTHR) B[i] = A[A[i]];
            __syncthreads();
            for (int i = threadIdx.x; i < NN; i += NTHR) A[i] = B[i];
            __syncthreads();
        }
        if (threadIdx.x == 0 && out_size > NN) {
            int start = (int)(0xFFFFFFFFu - (unsigned)(__ldcg(&g_skey) & 0xFFFFFFFFull));
            out[NN] = (float)A[start];
        }
    }
}

// ---------------- launch ----------------
extern "C" void kernel_launch(void* const* d_in, const int* in_sizes, int n_in,
                              void* d_out, int out_size) {
    const float* x    = (const float*)d_in[0];
    const int*   ei   = (const int*)  d_in[1];
    const float* W1   = (const float*)d_in[2];
    const float* as1  = (const float*)d_in[3];
    const float* ad1  = (const float*)d_in[4];
    const float* b1   = (const float*)d_in[5];
    const float* W2   = (const float*)d_in[6];
    const float* as2  = (const float*)d_in[7];
    const float* ad2  = (const float*)d_in[8];
    const float* b2   = (const float*)d_in[9];
    const float* W3   = (const float*)d_in[10];
    const float* as3  = (const float*)d_in[11];
    const float* ad3  = (const float*)d_in[12];
    const float* b3   = (const float*)d_in[13];
    const float* phi1 = (const float*)d_in[14];
    const float* phi2 = (const float*)d_in[15];
    float* out = (float*)d_out;

    gat_fused<<<NBLK, NTHR>>>(x, ei, W1, as1, ad1, b1, W2, as2, ad2, b2,
                              W3, as3, ad3, b3, phi1, phi2, out, out_size);
}

// round 3
// speedup vs baseline: 1.2230x; 1.2230x over previous
#include <cuda_runtime.h>
#include <math.h>

#define NN    4096
#define EE    131072
#define ETOT  (EE + NN)
#define NEG_SLOPE 0.2f
#define NBLK  64
#define NTHR  1024
#define NTOT  (NBLK * NTHR)

// ---- scratch: zero-initialized at module load; every launch restores zeros at exit ----
__device__ float              g_accA[NN * 3];
__device__ float              g_ssumA[NN];
__device__ float              g_accB[NN * 3];
__device__ float              g_ssumB[NN];
__device__ float              g_acc3[NN];
__device__ float              g_ssum3[NN];
__device__ float              g_w[NN];        // overwritten fully each launch
__device__ float              g_xf[NN];       // overwritten fully each launch
__device__ unsigned long long g_ckey[NN];
__device__ unsigned long long g_skey;
__device__ float              g_sumexp;
__device__ float              g_p12;          // overwritten each launch
__device__ unsigned           g_count;        // self-resetting
__device__ unsigned           g_gen;          // monotonic across launches (ok)

__device__ __forceinline__ void gsync() {
    __syncthreads();
    if (threadIdx.x == 0) {
        __threadfence();                              // release
        unsigned g = *(volatile unsigned*)&g_gen;     // read BEFORE arriving
        if (atomicAdd(&g_count, 1u) == (unsigned)(NBLK - 1)) {
            g_count = 0;
            __threadfence();
            *(volatile unsigned*)&g_gen = g + 1;
        } else {
            while (*(volatile unsigned*)&g_gen == g) __nanosleep(128);
            __threadfence();                          // acquire
        }
    }
    __syncthreads();
}

__device__ __forceinline__ unsigned int fenc(float f) {
    unsigned int u = __float_as_uint(f);
    return (u & 0x80000000u) ? ~u : (u | 0x80000000u);
}
__device__ __forceinline__ float leaky(float x) { return x >= 0.0f ? x : NEG_SLOPE * x; }
__device__ __forceinline__ float relu(float x)  { return x > 0.0f ? x : 0.0f; }

// layer-2 feature of node n, recomputed from layer-1 accumulators
__device__ __forceinline__ void z2_of(int n, const float* b1r, const float* W2r, float* z2) {
    float inv = 1.0f / (__ldcg(&g_ssumA[n]) + 1e-16f);
    float h0 = relu(__ldcg(&g_accA[n * 3 + 0]) * inv + b1r[0]);
    float h1 = relu(__ldcg(&g_accA[n * 3 + 1]) * inv + b1r[1]);
    float h2 = relu(__ldcg(&g_accA[n * 3 + 2]) * inv + b1r[2]);
#pragma unroll
    for (int k = 0; k < 3; k++)
        z2[k] = h0 * W2r[k * 3 + 0] + h1 * W2r[k * 3 + 1] + h2 * W2r[k * 3 + 2];
}

// layer-3 feature (scalar) of node n, from layer-2 accumulators
__device__ __forceinline__ float z3_of(int n, const float* b2r, const float* W3r) {
    float inv = 1.0f / (__ldcg(&g_ssumB[n]) + 1e-16f);
    float z = 0.f;
#pragma unroll
    for (int c = 0; c < 3; c++)
        z += relu(__ldcg(&g_accB[n * 3 + c]) * inv + b2r[c]) * W3r[c];
    return z;
}

__global__ __launch_bounds__(NTHR)
void gat_fused(const float* __restrict__ x,    const int* __restrict__ ei,
               const float* __restrict__ W1,   const float* __restrict__ as1,
               const float* __restrict__ ad1,  const float* __restrict__ b1,
               const float* __restrict__ W2,   const float* __restrict__ as2,
               const float* __restrict__ ad2,  const float* __restrict__ b2,
               const float* __restrict__ W3,   const float* __restrict__ as3,
               const float* __restrict__ ad3,  const float* __restrict__ b3,
               const float* __restrict__ phi1, const float* __restrict__ phi2,
               float* __restrict__ out, int out_size) {
    const int tid = blockIdx.x * NTHR + threadIdx.x;

    // ---- Ph1: layer-1 edge pass; z1 computed on the fly from x ----
    {
        float w1[3], s1[3], d1[3];
#pragma unroll
        for (int k = 0; k < 3; k++) { w1[k] = __ldg(W1 + k); s1[k] = __ldg(as1 + k); d1[k] = __ldg(ad1 + k); }
        for (int t = tid; t < ETOT; t += NTOT) {
            int s, d;
            if (t < EE) { s = __ldg(ei + t); d = __ldg(ei + EE + t); } else { s = t - EE; d = s; }
            float xs = __ldg(x + s), xd = __ldg(x + d);
            float zs = 0.f, zd = 0.f, z[3];
#pragma unroll
            for (int k = 0; k < 3; k++) {
                z[k] = xs * w1[k];
                zs += z[k] * s1[k];
                zd += (xd * w1[k]) * d1[k];
            }
            float w = __expf(leaky(zs + zd));   // softmax shift-invariant: no segment max needed
            atomicAdd(&g_ssumA[d], w);
#pragma unroll
            for (int k = 0; k < 3; k++) atomicAdd(&g_accA[d * 3 + k], w * z[k]);
        }
    }
    gsync();

    // ---- Ph2: layer-2 edge pass; h1/z2 recomputed per endpoint ----
    {
        float b1r[3], W2r[9], s2[3], d2[3];
#pragma unroll
        for (int k = 0; k < 3; k++) { b1r[k] = __ldg(b1 + k); s2[k] = __ldg(as2 + k); d2[k] = __ldg(ad2 + k); }
#pragma unroll
        for (int k = 0; k < 9; k++) W2r[k] = __ldg(W2 + k);
        for (int t = tid; t < ETOT; t += NTOT) {
            int s, d;
            if (t < EE) { s = __ldg(ei + t); d = __ldg(ei + EE + t); } else { s = t - EE; d = s; }
            float zS[3], zD[3];
            z2_of(s, b1r, W2r, zS);
            z2_of(d, b1r, W2r, zD);
            float zs = zS[0]*s2[0] + zS[1]*s2[1] + zS[2]*s2[2];
            float zd = zD[0]*d2[0] + zD[1]*d2[1] + zD[2]*d2[2];
            float w = __expf(leaky(zs + zd));
            atomicAdd(&g_ssumB[d], w);
#pragma unroll
            for (int k = 0; k < 3; k++) atomicAdd(&g_accB[d * 3 + k], w * zS[k]);
        }
    }
    gsync();

    // ---- Ph3: layer-3 edge pass (HID=1) ----
    {
        float b2r[3], W3r[3];
#pragma unroll
        for (int k = 0; k < 3; k++) { b2r[k] = __ldg(b2 + k); W3r[k] = __ldg(W3 + k); }
        float a3s = __ldg(as3), a3d = __ldg(ad3);
        for (int t = tid; t < ETOT; t += NTOT) {
            int s, d;
            if (t < EE) { s = __ldg(ei + t); d = __ldg(ei + EE + t); } else { s = t - EE; d = s; }
            float zS = z3_of(s, b2r, W3r);
            float zD = z3_of(d, b2r, W3r);
            float w = __expf(leaky(zS * a3s + zD * a3d));
            atomicAdd(&g_ssum3[d], w);
            atomicAdd(&g_acc3[d], w * zS);
        }
    }
    gsync();

    // ---- Ph4: node logits -> exp + global sum; p12 dot ----
    if (tid < NN) {
        float o = __ldcg(&g_acc3[tid]) / (__ldcg(&g_ssum3[tid]) + 1e-16f) + __ldg(b3);
        float w = expf(o);
        g_w[tid] = w;
        atomicAdd(&g_sumexp, w);
    }
    if (blockIdx.x == 0 && threadIdx.x < 32) {
        int l = threadIdx.x;
        float p = 0.f;
#pragma unroll
        for (int k = 0; k < 4; k++) p += __ldg(phi1 + l + 32 * k) * __ldg(phi2 + l + 32 * k);
#pragma unroll
        for (int off = 16; off > 0; off >>= 1) p += __shfl_down_sync(0xFFFFFFFFu, p, off);
        if (l == 0) g_p12 = p;
    }
    gsync();

    // ---- Ph5: normalize -> out + xf; argmax(start) 64-bit key ----
    if (tid < NN) {
        float xo = g_w[tid] / __ldcg(&g_sumexp);
        out[tid]  = xo;
        g_xf[tid] = xo;
        unsigned long long key =
            ((unsigned long long)fenc(xo) << 32) |
            (unsigned long long)(0xFFFFFFFFu - (unsigned)tid);
        atomicMax(&g_skey, key);
    }
    gsync();

    // ---- Ph6: chain scores -> per-source argmax key ----
    {
        const float scale = 1.0f / sqrtf(128.0f);
        float p12 = __ldcg(&g_p12);
        for (int j = tid; j < EE; j += NTOT) {
            int s = __ldg(ei + j), d = __ldg(ei + EE + j);
            float t = ((p12 * __ldcg(g_xf + s)) * __ldcg(g_xf + d)) * scale;
            float sc = tanhf(t);
            unsigned long long key =
                ((unsigned long long)fenc(sc) << 32) |
                (unsigned long long)(0xFFFFFFFFu - (unsigned)j);
            atomicMax(&g_ckey[s], key);
        }
    }
    gsync();

    // ---- Ph7: block 0 walks; other blocks restore the all-zeros invariant ----
    if (blockIdx.x == 0) {
        __shared__ int A[NN];
        __shared__ int B[NN];
        for (int i = threadIdx.x; i < NN; i += NTHR) {
            unsigned long long key = __ldcg(&g_ckey[i]);
            g_ckey[i] = 0ull;                               // block 0 is sole reader
            int j = key ? (int)(0xFFFFFFFFu - (unsigned)(key & 0xFFFFFFFFull)) : 0;
            A[i] = __ldg(ei + EE + j);
        }
        __syncthreads();
        for (int it = 0; it < 12; it++) {                   // next^(2^12) = next^4096
            for (int i = threadIdx.x; i < NN; i += NTHR) B[i] = A[A[i]];
            __syncthreads();
            for (int i = threadIdx.x; i < NN; i += NTHR) A[i] = B[i];
            __syncthreads();
        }
        if (threadIdx.x == 0) {
            unsigned long long sk = __ldcg(&g_skey);
            g_skey = 0ull;
            g_sumexp = 0.f;
            int start = (int)(0xFFFFFFFFu - (unsigned)(sk & 0xFFFFFFFFull));
            if (out_size > NN) out[NN] = (float)A[start];
        }
    } else {
        const int zt = (blockIdx.x - 1) * NTHR + threadIdx.x;
        const int ZT = (NBLK - 1) * NTHR;
        for (int i = zt; i < NN * 3; i += ZT) { g_accA[i] = 0.f; g_accB[i] = 0.f; }
        for (int i = zt; i < NN; i += ZT) {
            g_ssumA[i] = 0.f; g_ssumB[i] = 0.f; g_acc3[i] = 0.f; g_ssum3[i] = 0.f;
        }
    }
}

// ---------------- launch ----------------
extern "C" void kernel_launch(void* const* d_in, const int* in_sizes, int n_in,
                              void* d_out, int out_size) {
    const float* x    = (const float*)d_in[0];
    const int*   ei   = (const int*)  d_in[1];
    const float* W1   = (const float*)d_in[2];
    const float* as1  = (const float*)d_in[3];
    const float* ad1  = (const float*)d_in[4];
    const float* b1   = (const float*)d_in[5];
    const float* W2   = (const float*)d_in[6];
    const float* as2  = (const float*)d_in[7];
    const float* ad2  = (const float*)d_in[8];
    const float* b2   = (const float*)d_in[9];
    const float* W3   = (const float*)d_in[10];
    const float* as3  = (const float*)d_in[11];
    const float* ad3  = (const float*)d_in[12];
    const float* b3   = (const float*)d_in[13];
    const float* phi1 = (const float*)d_in[14];
    const float* phi2 = (const float*)d_in[15];
    float* out = (float*)d_out;

    gat_fused<<<NBLK, NTHR>>>(x, ei, W1, as1, ad1, b1, W2, as2, ad2, b2,
                              W3, as3, ad3, b3, phi1, phi2, out, out_size);
}

// round 4
// speedup vs baseline: 2.0615x; 1.6856x over previous
#include <cuda_runtime.h>
#include <math.h>

#define NN    4096
#define EE    131072
#define ETOT  (EE + NN)
#define NEG_SLOPE 0.2f

// ---- scratch: zero-initialized at module load; every launch restores zeros at exit ----
__device__ float              g_accA[NN * 3];
__device__ float              g_ssumA[NN];
__device__ float              g_accB[NN * 3];
__device__ float              g_ssumB[NN];
__device__ float              g_acc3[NN];
__device__ float              g_ssum3[NN];
__device__ float              g_xf[NN];       // fully overwritten each launch
__device__ unsigned long long g_ckey[NN];     // zeroed by k_walk after reading
__device__ float              g_p12;          // overwritten each launch
__device__ int                g_start;        // overwritten each launch

__device__ __forceinline__ unsigned int fenc(float f) {
    unsigned int u = __float_as_uint(f);
    return (u & 0x80000000u) ? ~u : (u | 0x80000000u);
}
__device__ __forceinline__ float leaky(float x) { return x >= 0.0f ? x : NEG_SLOPE * x; }
__device__ __forceinline__ float relu(float x)  { return x > 0.0f ? x : 0.0f; }

// -------- kernel 1: layer-1 edge pass (z1 recomputed on the fly from x) --------
__global__ void k_edge1(const float* __restrict__ x, const int* __restrict__ ei,
                        const float* __restrict__ W1, const float* __restrict__ as1,
                        const float* __restrict__ ad1) {
    int t = blockIdx.x * blockDim.x + threadIdx.x;
    if (t >= ETOT) return;
    int s, d;
    if (t < EE) { s = __ldg(ei + t); d = __ldg(ei + EE + t); } else { s = t - EE; d = s; }
    float xs = __ldg(x + s), xd = __ldg(x + d);
    float zs = 0.f, zd = 0.f, z[3];
#pragma unroll
    for (int k = 0; k < 3; k++) {
        float w1k = __ldg(W1 + k);
        z[k] = xs * w1k;
        zs += z[k] * __ldg(as1 + k);
        zd += (xd * w1k) * __ldg(ad1 + k);
    }
    float w = __expf(leaky(zs + zd));            // softmax shift-invariant: no segment max
    atomicAdd(&g_ssumA[d], w);
#pragma unroll
    for (int k = 0; k < 3; k++) atomicAdd(&g_accA[d * 3 + k], w * z[k]);
}

// layer-2 feature recomputed from layer-1 accumulators (plain loads: fresh launch)
__device__ __forceinline__ void z2_of(int n, const float* b1r, const float* W2r, float* z2) {
    float inv = 1.0f / (g_ssumA[n] + 1e-16f);
    float h0 = relu(g_accA[n * 3 + 0] * inv + b1r[0]);
    float h1 = relu(g_accA[n * 3 + 1] * inv + b1r[1]);
    float h2 = relu(g_accA[n * 3 + 2] * inv + b1r[2]);
#pragma unroll
    for (int k = 0; k < 3; k++)
        z2[k] = h0 * W2r[k * 3 + 0] + h1 * W2r[k * 3 + 1] + h2 * W2r[k * 3 + 2];
}

// -------- kernel 2: layer-2 edge pass --------
__global__ void k_edge2(const int* __restrict__ ei, const float* __restrict__ b1,
                        const float* __restrict__ W2, const float* __restrict__ as2,
                        const float* __restrict__ ad2) {
    int t = blockIdx.x * blockDim.x + threadIdx.x;
    if (t >= ETOT) return;
    float b1r[3], W2r[9];
#pragma unroll
    for (int k = 0; k < 3; k++) b1r[k] = __ldg(b1 + k);
#pragma unroll
    for (int k = 0; k < 9; k++) W2r[k] = __ldg(W2 + k);
    int s, d;
    if (t < EE) { s = __ldg(ei + t); d = __ldg(ei + EE + t); } else { s = t - EE; d = s; }
    float zS[3], zD[3];
    z2_of(s, b1r, W2r, zS);
    z2_of(d, b1r, W2r, zD);
    float zs = 0.f, zd = 0.f;
#pragma unroll
    for (int k = 0; k < 3; k++) { zs += zS[k] * __ldg(as2 + k); zd += zD[k] * __ldg(ad2 + k); }
    float w = __expf(leaky(zs + zd));
    atomicAdd(&g_ssumB[d], w);
#pragma unroll
    for (int k = 0; k < 3; k++) atomicAdd(&g_accB[d * 3 + k], w * zS[k]);
}

__device__ __forceinline__ float z3_of(int n, const float* b2r, const float* W3r) {
    float inv = 1.0f / (g_ssumB[n] + 1e-16f);
    float z = 0.f;
#pragma unroll
    for (int c = 0; c < 3; c++)
        z += relu(g_accB[n * 3 + c] * inv + b2r[c]) * W3r[c];
    return z;
}

// -------- kernel 3: layer-3 edge pass (HID=1) --------
__global__ void k_edge3(const int* __restrict__ ei, const float* __restrict__ b2,
                        const float* __restrict__ W3, const float* __restrict__ as3,
                        const float* __restrict__ ad3) {
    int t = blockIdx.x * blockDim.x + threadIdx.x;
    if (t >= ETOT) return;
    float b2r[3], W3r[3];
#pragma unroll
    for (int k = 0; k < 3; k++) { b2r[k] = __ldg(b2 + k); W3r[k] = __ldg(W3 + k); }
    int s, d;
    if (t < EE) { s = __ldg(ei + t); d = __ldg(ei + EE + t); } else { s = t - EE; d = s; }
    float zS = z3_of(s, b2r, W3r);
    float zD = z3_of(d, b2r, W3r);
    float w = __expf(leaky(zS * __ldg(as3) + zD * __ldg(ad3)));
    atomicAdd(&g_ssum3[d], w);
    atomicAdd(&g_acc3[d], w * zS);
}

// -------- kernel 4: softmax + start argmax + p12 (one block, no global atomics) --------
__global__ void k_softmax(const float* __restrict__ b3, const float* __restrict__ phi1,
                          const float* __restrict__ phi2, float* __restrict__ out) {
    __shared__ float sred[1024];
    __shared__ unsigned long long skey[1024];
    int tid = threadIdx.x;
    float b = __ldg(b3);
    float v[4];
    float lsum = 0.f;
#pragma unroll
    for (int r = 0; r < 4; r++) {
        int i = tid + r * 1024;
        float o = g_acc3[i] / (g_ssum3[i] + 1e-16f) + b;
        v[r] = expf(o);
        lsum += v[r];
    }
    sred[tid] = lsum; __syncthreads();
    for (int s = 512; s > 0; s >>= 1) { if (tid < s) sred[tid] += sred[tid + s]; __syncthreads(); }
    float sum = sred[0]; __syncthreads();

    unsigned long long lkey = 0ull;
#pragma unroll
    for (int r = 0; r < 4; r++) {
        int i = tid + r * 1024;
        float xo = v[r] / sum;
        out[i]  = xo;
        g_xf[i] = xo;
        unsigned long long k =
            ((unsigned long long)fenc(xo) << 32) | (unsigned long long)(0xFFFFFFFFu - (unsigned)i);
        if (k > lkey) lkey = k;
    }
    skey[tid] = lkey; __syncthreads();
    for (int s = 512; s > 0; s >>= 1) { if (tid < s) skey[tid] = max(skey[tid], skey[tid + s]); __syncthreads(); }

    if (tid < 128) sred[tid] = __ldg(phi1 + tid) * __ldg(phi2 + tid);
    __syncthreads();
    for (int s = 64; s > 0; s >>= 1) { if (tid < s) sred[tid] += sred[tid + s]; __syncthreads(); }
    if (tid == 0) {
        g_p12   = sred[0];
        g_start = (int)(0xFFFFFFFFu - (unsigned)(skey[0] & 0xFFFFFFFFull));
    }
}

// -------- kernel 5: per-edge chain keys; also zero the dead GAT accumulators --------
__global__ void k_ckey(const int* __restrict__ ei) {
    int j = blockIdx.x * blockDim.x + threadIdx.x;   // 0..EE-1 exactly
    {
        int s = __ldg(ei + j), d = __ldg(ei + EE + j);
        const float scale = 1.0f / sqrtf(128.0f);
        float t = ((g_p12 * g_xf[s]) * g_xf[d]) * scale;  // match reference mul order
        float sc = tanhf(t);                               // CONST == 1.0
        unsigned long long key =
            ((unsigned long long)fenc(sc) << 32) | (unsigned long long)(0xFFFFFFFFu - (unsigned)j);
        atomicMax(&g_ckey[s], key);
    }
    // restore all-zeros invariant on accumulators (dead at this point)
    if (j < NN * 3) { g_accA[j] = 0.f; g_accB[j] = 0.f; }
    else if (j < NN * 3 + NN)     g_ssumA[j - NN * 3] = 0.f;
    else if (j < NN * 3 + NN * 2) g_ssumB[j - NN * 3 - NN] = 0.f;
    else if (j < NN * 3 + NN * 3) g_acc3 [j - NN * 3 - NN * 2] = 0.f;
    else if (j < NN * 3 + NN * 4) g_ssum3[j - NN * 3 - NN * 3] = 0.f;
}

// -------- kernel 6: resolve next[], pointer-double the 4096-step walk, zero ckey --------
__global__ void k_walk(const int* __restrict__ ei, float* __restrict__ out, int out_size) {
    __shared__ int A[NN];
    __shared__ int B[NN];
    int tid = threadIdx.x;
#pragma unroll
    for (int r = 0; r < 4; r++) {
        int i = tid + r * 1024;
        unsigned long long key = g_ckey[i];
        g_ckey[i] = 0ull;                              // sole reader; reset for next launch
        int j = key ? (int)(0xFFFFFFFFu - (unsigned)(key & 0xFFFFFFFFull)) : 0;
        A[i] = __ldg(ei + EE + j);
    }
    __syncthreads();
    for (int it = 0; it < 12; it++) {                  // next^(2^12) = next^4096
#pragma unroll
        for (int r = 0; r < 4; r++) { int i = tid + r * 1024; B[i] = A[A[i]]; }
        __syncthreads();
#pragma unroll
        for (int r = 0; r < 4; r++) { int i = tid + r * 1024; A[i] = B[i]; }
        __syncthreads();
    }
    if (tid == 0 && out_size > NN) out[NN] = (float)A[g_start];
}

// ---------------- launch ----------------
extern "C" void kernel_launch(void* const* d_in, const int* in_sizes, int n_in,
                              void* d_out, int out_size) {
    const float* x    = (const float*)d_in[0];
    const int*   ei   = (const int*)  d_in[1];
    const float* W1   = (const float*)d_in[2];
    const float* as1  = (const float*)d_in[3];
    const float* ad1  = (const float*)d_in[4];
    const float* b1   = (const float*)d_in[5];
    const float* W2   = (const float*)d_in[6];
    const float* as2  = (const float*)d_in[7];
    const float* ad2  = (const float*)d_in[8];
    const float* b2   = (const float*)d_in[9];
    const float* W3   = (const float*)d_in[10];
    const float* as3  = (const float*)d_in[11];
    const float* ad3  = (const float*)d_in[12];
    const float* b3   = (const float*)d_in[13];
    const float* phi1 = (const float*)d_in[14];
    const float* phi2 = (const float*)d_in[15];
    float* out = (float*)d_out;

    const int NB_E = (ETOT + 255) / 256;   // 528
    const int NB_C = EE / 256;             // 512 (EE divisible by 256)

    k_edge1<<<NB_E, 256>>>(x, ei, W1, as1, ad1);
    k_edge2<<<NB_E, 256>>>(ei, b1, W2, as2, ad2);
    k_edge3<<<NB_E, 256>>>(ei, b2, W3, as3, ad3);
    k_softmax<<<1, 1024>>>(b3, phi1, phi2, out);
    k_ckey<<<NB_C, 256>>>(ei);
    k_walk<<<1, 1024>>>(ei, out, out_size);
}